// round 6
// baseline (speedup 1.0000x reference)
#include <cuda_runtime.h>
#include <cuda_bf16.h>
#include <cstdint>

// ---------------------------------------------------------------------------
// QuantumLayer fused single-kernel (persistent CTAs):
//   out[b,m] = e^{i*kappa*m^2} * sum_n G[m,n] * state[b,n]
// GEMM form: out[B,64] = X[B,64] @ W[64,64], X=[re|im],
//   cols 2m/2m+1 = Re/Im (Kerr folded into W).
// bf16 mma.m16n8k16, hi/lo split: D = Xh*Wh + Xl*Wh + Xh*Wl.
//
// Warp 0 of every CTA builds W (fp32 recurrence, matches reference's own
// complex64 arithmetic; Kerr angle computed exactly as JAX fp32 then fp64
// sincos) straight into the fragment-native smem layout. Then the CTA
// grid-strides over 256-state tiles.  ONE kernel node, no inter-kernel gap.
// ---------------------------------------------------------------------------

#define TPB 256

struct fc { float re, im; };
__device__ __forceinline__ fc cmul(fc a, fc b){ return {a.re*b.re - a.im*b.im, a.re*b.im + a.im*b.re}; }
__device__ __forceinline__ fc cadd(fc a, fc b){ return {a.re + b.re, a.im + b.im}; }
__device__ __forceinline__ fc cscale(fc a, float s){ return {a.re*s, a.im*s}; }

// Build W into sW (fragment-native, row stride 17 uint4). Warp-0 collective.
__device__ void build_W_smem(uint4* sW,
                             const float* gre, const float* gim,
                             const float* phip, const float* zrep,
                             const float* zimp, const float* kapp)
{
    const int m = threadIdx.x;  // lane 0..31 == Fock row index
    const float gr  = gre[0],  gi  = gim[0];
    const float ph  = phip[0];
    const float zr  = zrep[0], zi  = zimp[0];
    const float kap = kapp[0];

    const float sq_m  = sqrtf((float)m);
    const float rsq_m = (m > 0) ? 1.0f / sq_m : 0.0f;
    auto SQ  = [&](int k){ return __shfl_sync(0xffffffffu, sq_m,  k); };
    auto RSQ = [&](int k){ return __shfl_sync(0xffffffffu, rsq_m, k); };

    const float r = sqrtf(zr*zr + zi*zi);
    fc eid;                                   // e^{i delta} = zeta/|zeta|
    if (r > 0.0f) { eid = { zr / r, zi / r }; } else { eid = { 1.0f, 0.0f }; }

    const float er   = expf(r);
    const float eiv  = 1.0f / er;
    const float chv  = 0.5f * (er + eiv);
    const float T    = (0.5f * (er - eiv)) / chv;  // tanh r
    const float sech = 1.0f / chv;

    float sph, cph; sincosf(ph, &sph, &cph);
    const fc eiphi  = { cph, sph };
    const fc e2iphi = cmul(eiphi, eiphi);
    const fc eidp   = cmul(eid, e2iphi);      // e^{i(delta + 2 phi)}

    const fc gamma = { gr,  gi };
    const fc gbar  = { gr, -gi };

    // g00
    const fc gb2 = cmul(gbar, gbar);
    const fc t1  = cscale(cmul(gb2, eidp), T);
    const float zr_ = -0.5f*(gr*gr + gi*gi + t1.re);
    const float zi_ = -0.5f*t1.im;
    float s0, c0p; sincosf(zi_, &s0, &c0p);
    const float ez = expf(zr_) * sqrtf(sech);
    const fc g00 = { ez * c0p, ez * s0 };

    const fc A  = cadd(gamma, cscale(cmul(gbar, eidp), T));
    const fc Bc = cscale(eidp, T);
    const fc P  = cscale(eiphi, sech);
    const fc Q  = { eid.re * T, -eid.im * T };   // e^{-i delta} tanh r

    // column 0 (serial, replicated; lane keeps its row m)
    fc c0 = g00;
    {
        fc gm1 = g00, gm2 = {0.0f, 0.0f};
        for (int k = 1; k < 32; k++) {
            fc ag = cmul(A, gm1);
            fc bg = cscale(cmul(Bc, gm2), SQ(k - 1));
            fc g  = cscale({ag.re - bg.re, ag.im - bg.im}, RSQ(k));
            if (m == k) c0 = g;
            gm2 = gm1; gm1 = g;
        }
    }

    // Kerr phase: angle computed exactly as the fp32 reference ((kap*m)*m),
    // then accurate fp64 sincos of that angle (range reduction matters).
    const float angf = (kap * (float)m) * (float)m;
    double skd, ckd; sincos((double)angf, &skd, &ckd);
    const fc kerr = { (float)ckd, (float)skd };

    auto put = [&](int j, int k, float x){
        __nv_bfloat16 h = __float2bfloat16(x);
        float l = x - __bfloat162float(h);
        // N-permutation: gmem col -> storage row js
        int u  = j >> 4, rem = j & 15;
        int tt = rem >> 2, w4 = rem & 3;
        int js = (2*u + (w4 >> 1)) * 8 + 2*tt + (w4 & 1);
        // K location: chunk c, thread tq, quad q
        int c = k >> 4, tq = (k >> 2) & 3, q = k & 3;
        __nv_bfloat16* base = reinterpret_cast<__nv_bfloat16*>(&sW[js*17 + c*4 + tq]);
        base[q]     = h;                       // words x,y = b0h,b1h
        base[4 + q] = __float2bfloat16(l);     // words z,w = b0l,b1l
    };
    auto write_col = [&](int n, fc v){
        fc w = cmul(kerr, v);
        put(2*m,     n,      w.re);
        put(2*m + 1, n,      w.im);
        put(2*m,     32 + n, -w.im);
        put(2*m + 1, 32 + n, w.re);
    };

    fc cur = c0, prev = {0.0f, 0.0f};
    write_col(0, cur);

    for (int n = 0; n < 31; n++) {
        float ur = __shfl_up_sync(0xffffffffu, cur.re, 1);
        float ui = __shfl_up_sync(0xffffffffu, cur.im, 1);
        if (m == 0) { ur = 0.0f; ui = 0.0f; }
        fc gc = cmul(gbar, cur);
        fc term = { sq_m * ur - gc.re, sq_m * ui - gc.im };
        fc pt = cmul(P, term);
        fc qp = cscale(cmul(Q, prev), SQ(n));
        fc next = cscale({pt.re + qp.re, pt.im + qp.im}, RSQ(n + 1));
        prev = cur; cur = next;
        write_col(n + 1, cur);
    }
}

// ============================ mma machinery ===============================

__device__ __forceinline__ void split2(float x, float y, uint32_t& h, uint32_t& l)
{
    uint32_t hh;
    asm("cvt.rn.bf16x2.f32 %0, %1, %2;" : "=r"(hh) : "f"(y), "f"(x)); // lo=x, hi=y
    float hx = __uint_as_float(hh << 16);
    float hy = __uint_as_float(hh & 0xffff0000u);
    float lx = x - hx;
    float ly = y - hy;
    uint32_t ll;
    asm("cvt.rn.bf16x2.f32 %0, %1, %2;" : "=r"(ll) : "f"(ly), "f"(lx));
    h = hh; l = ll;
}

__device__ __forceinline__ void mma_bf16(float* c,
                                         uint32_t a0, uint32_t a1, uint32_t a2, uint32_t a3,
                                         uint32_t b0, uint32_t b1)
{
    asm("mma.sync.aligned.m16n8k16.row.col.f32.bf16.bf16.f32 "
        "{%0,%1,%2,%3}, {%4,%5,%6,%7}, {%8,%9}, {%0,%1,%2,%3};"
        : "+f"(c[0]), "+f"(c[1]), "+f"(c[2]), "+f"(c[3])
        : "r"(a0), "r"(a1), "r"(a2), "r"(a3), "r"(b0), "r"(b1));
}

template <bool FULL>
__device__ __forceinline__ void do_tile(
    const float* __restrict__ sre, const float* __restrict__ sim,
    float* __restrict__ out, int B, const uint4* sW, int tile,
    int warp, int g, int t)
{
    const int wbase = tile * 256 + warp * 32;

    int row0[2], row1[2];
#pragma unroll
    for (int tl = 0; tl < 2; tl++) {
        row0[tl] = wbase + tl * 16 + g;
        row1[tl] = row0[tl] + 8;
    }

    // front-batched A loads: 16x LDG.128
    float4 L[16];
#pragma unroll
    for (int tl = 0; tl < 2; tl++) {
        int rc0 = row0[tl], rc1 = row1[tl];
        if (!FULL) { rc0 = (rc0 < B) ? rc0 : (B - 1); rc1 = (rc1 < B) ? rc1 : (B - 1); }
        const float4* pr0 = reinterpret_cast<const float4*>(sre + (size_t)rc0 * 32);
        const float4* pi0 = reinterpret_cast<const float4*>(sim + (size_t)rc0 * 32);
        const float4* pr1 = reinterpret_cast<const float4*>(sre + (size_t)rc1 * 32);
        const float4* pi1 = reinterpret_cast<const float4*>(sim + (size_t)rc1 * 32);
        L[tl * 8 + 0] = pr0[t];
        L[tl * 8 + 1] = pr0[t + 4];
        L[tl * 8 + 2] = pi0[t];
        L[tl * 8 + 3] = pi0[t + 4];
        L[tl * 8 + 4] = pr1[t];
        L[tl * 8 + 5] = pr1[t + 4];
        L[tl * 8 + 6] = pi1[t];
        L[tl * 8 + 7] = pi1[t + 4];
    }

    // A fragments
    uint32_t Ah[2][4][4], Al[2][4][4];
#pragma unroll
    for (int tl = 0; tl < 2; tl++) {
#pragma unroll
        for (int kt = 0; kt < 4; kt++) {
            float4 v0 = L[tl * 8 + kt];
            float4 v1 = L[tl * 8 + 4 + kt];
            split2(v0.x, v0.y, Ah[tl][kt][0], Al[tl][kt][0]);
            split2(v0.z, v0.w, Ah[tl][kt][2], Al[tl][kt][2]);
            split2(v1.x, v1.y, Ah[tl][kt][1], Al[tl][kt][1]);
            split2(v1.z, v1.w, Ah[tl][kt][3], Al[tl][kt][3]);
        }
    }

#pragma unroll
    for (int u = 0; u < 4; u++) {
        float acc[2][2][4];                 // [ntHalf][tile][frag]
#pragma unroll
        for (int a = 0; a < 2; a++)
#pragma unroll
            for (int b = 0; b < 2; b++)
#pragma unroll
                for (int c = 0; c < 4; c++) acc[a][b][c] = 0.f;

#pragma unroll
        for (int h2 = 0; h2 < 2; h2++) {
            const int nt = 2 * u + h2;
            const uint4* bp = &sW[(nt * 8 + g) * 17 + t];
#pragma unroll
            for (int kt = 0; kt < 4; kt++) {
                uint4 b = bp[kt * 4];       // {b0h, b1h, b0l, b1l}
#pragma unroll
                for (int tl = 0; tl < 2; tl++) {
                    mma_bf16(acc[h2][tl], Ah[tl][kt][0], Ah[tl][kt][1],
                                          Ah[tl][kt][2], Ah[tl][kt][3], b.x, b.y);
                    mma_bf16(acc[h2][tl], Al[tl][kt][0], Al[tl][kt][1],
                                          Al[tl][kt][2], Al[tl][kt][3], b.x, b.y);
                    mma_bf16(acc[h2][tl], Ah[tl][kt][0], Ah[tl][kt][1],
                                          Ah[tl][kt][2], Ah[tl][kt][3], b.z, b.w);
                }
            }
        }

        const int colb = 16 * u + 4 * t;
#pragma unroll
        for (int tl = 0; tl < 2; tl++) {
            if (FULL || row0[tl] < B) {
                float4 v = make_float4(acc[0][tl][0], acc[0][tl][1],
                                       acc[1][tl][0], acc[1][tl][1]);
                *reinterpret_cast<float4*>(out + (size_t)row0[tl] * 64 + colb) = v;
            }
            if (FULL || row1[tl] < B) {
                float4 v = make_float4(acc[0][tl][2], acc[0][tl][3],
                                       acc[1][tl][2], acc[1][tl][3]);
                *reinterpret_cast<float4*>(out + (size_t)row1[tl] * 64 + colb) = v;
            }
        }
    }
}

template <bool FULL>
__global__ void __launch_bounds__(TPB, 2)
fused_k(const float* __restrict__ sre, const float* __restrict__ sim,
        float* __restrict__ out, int B, int ntiles,
        const float* __restrict__ gre, const float* __restrict__ gim,
        const float* __restrict__ phip, const float* __restrict__ zrep,
        const float* __restrict__ zimp, const float* __restrict__ kapp)
{
    __shared__ uint4 sW[64 * 17];

    if (threadIdx.x < 32)
        build_W_smem(sW, gre, gim, phip, zrep, zimp, kapp);
    __syncthreads();

    const int warp = threadIdx.x >> 5;
    const int lane = threadIdx.x & 31;
    const int g    = lane >> 2;
    const int t    = lane & 3;

    for (int tile = blockIdx.x; tile < ntiles; tile += gridDim.x) {
        if (FULL || (tile + 1) * 256 <= B)
            do_tile<true>(sre, sim, out, B, sW, tile, warp, g, t);
        else
            do_tile<false>(sre, sim, out, B, sW, tile, warp, g, t);
    }
}

extern "C" void kernel_launch(void* const* d_in, const int* in_sizes, int n_in,
                              void* d_out, int out_size)
{
    const float* state_re = (const float*)d_in[0];
    const float* state_im = (const float*)d_in[1];
    const float* gamma_re = (const float*)d_in[2];
    const float* gamma_im = (const float*)d_in[3];
    const float* phi      = (const float*)d_in[4];
    const float* zeta_re  = (const float*)d_in[5];
    const float* zeta_im  = (const float*)d_in[6];
    const float* kappa    = (const float*)d_in[7];

    const int B = in_sizes[0] / 32;
    const int ntiles = (B + 255) / 256;

    int sms = 148;
    cudaDeviceGetAttribute(&sms, cudaDevAttrMultiProcessorCount, 0);
    int blocks = 2 * sms;
    if (blocks > ntiles) blocks = ntiles;

    if ((B & 255) == 0) {
        fused_k<true><<<blocks, TPB>>>(state_re, state_im, (float*)d_out, B, ntiles,
                                       gamma_re, gamma_im, phi, zeta_re, zeta_im, kappa);
    } else {
        fused_k<false><<<blocks, TPB>>>(state_re, state_im, (float*)d_out, B, ntiles,
                                        gamma_re, gamma_im, phi, zeta_re, zeta_im, kappa);
    }
}

// round 7
// speedup vs baseline: 1.7787x; 1.7787x over previous
#include <cuda_runtime.h>
#include <cuda_bf16.h>
#include <cstdint>

// ---------------------------------------------------------------------------
// QuantumLayer: out[b,m] = e^{i*kappa*m^2} * sum_n G[m,n] * state[b,n]
// GEMM form: out[B,64] = X[B,64] @ W[64,64], X=[re|im],
//   cols 2m/2m+1 = Re/Im (Kerr folded into W).
// bf16 mma.m16n8k16, hi/lo split: D = Xh*Wh + Xl*Wh + Xh*Wl.
//
// Round 7: R4's proven apply_k (101 us) + fast fp32 build_G (R6-validated)
// to shrink the inter-kernel gap. Two kernel nodes, no PDL, no persistence.
// ---------------------------------------------------------------------------

#define TPB 256

// [js][ 4*kt + t ] uint4, row stride 17 (16 + 1 pad).
__device__ uint4 g_Wf[64 * 17];

// ======================== build W (1 warp, fp32) ===========================
struct fc { float re, im; };
__device__ __forceinline__ fc cmul(fc a, fc b){ return {a.re*b.re - a.im*b.im, a.re*b.im + a.im*b.re}; }
__device__ __forceinline__ fc cadd(fc a, fc b){ return {a.re + b.re, a.im + b.im}; }
__device__ __forceinline__ fc cscale(fc a, float s){ return {a.re*s, a.im*s}; }

__global__ void build_G(const float* __restrict__ gre, const float* __restrict__ gim,
                        const float* __restrict__ phip, const float* __restrict__ zrep,
                        const float* __restrict__ zimp, const float* __restrict__ kapp)
{
    const int m = threadIdx.x;  // lane 0..31 == Fock row index
    const float gr  = gre[0],  gi  = gim[0];
    const float ph  = phip[0];
    const float zr  = zrep[0], zi  = zimp[0];
    const float kap = kapp[0];

    const float sq_m  = sqrtf((float)m);
    const float rsq_m = (m > 0) ? 1.0f / sq_m : 0.0f;
    auto SQ  = [&](int k){ return __shfl_sync(0xffffffffu, sq_m,  k); };
    auto RSQ = [&](int k){ return __shfl_sync(0xffffffffu, rsq_m, k); };

    const float r = sqrtf(zr*zr + zi*zi);
    fc eid;                                   // e^{i delta} = zeta/|zeta|
    if (r > 0.0f) { eid = { zr / r, zi / r }; } else { eid = { 1.0f, 0.0f }; }

    const float er   = expf(r);
    const float eiv  = 1.0f / er;
    const float chv  = 0.5f * (er + eiv);
    const float T    = (0.5f * (er - eiv)) / chv;  // tanh r
    const float sech = 1.0f / chv;

    float sph, cph; sincosf(ph, &sph, &cph);
    const fc eiphi  = { cph, sph };
    const fc e2iphi = cmul(eiphi, eiphi);
    const fc eidp   = cmul(eid, e2iphi);      // e^{i(delta + 2 phi)}

    const fc gamma = { gr,  gi };
    const fc gbar  = { gr, -gi };

    // g00
    const fc gb2 = cmul(gbar, gbar);
    const fc t1  = cscale(cmul(gb2, eidp), T);
    const float zr_ = -0.5f*(gr*gr + gi*gi + t1.re);
    const float zi_ = -0.5f*t1.im;
    float s0, c0p; sincosf(zi_, &s0, &c0p);
    const float ez = expf(zr_) * sqrtf(sech);
    const fc g00 = { ez * c0p, ez * s0 };

    const fc A  = cadd(gamma, cscale(cmul(gbar, eidp), T));
    const fc Bc = cscale(eidp, T);
    const fc P  = cscale(eiphi, sech);
    const fc Q  = { eid.re * T, -eid.im * T };   // e^{-i delta} tanh r

    // column 0 (serial, replicated; lane keeps its row m)
    fc c0 = g00;
    {
        fc gm1 = g00, gm2 = {0.0f, 0.0f};
        for (int k = 1; k < 32; k++) {
            fc ag = cmul(A, gm1);
            fc bg = cscale(cmul(Bc, gm2), SQ(k - 1));
            fc g  = cscale({ag.re - bg.re, ag.im - bg.im}, RSQ(k));
            if (m == k) c0 = g;
            gm2 = gm1; gm1 = g;
        }
    }

    // Kerr: angle exactly as the fp32 reference ((kap*m)*m), fp64 sincos.
    const float angf = (kap * (float)m) * (float)m;
    double skd, ckd; sincos((double)angf, &skd, &ckd);
    const fc kerr = { (float)ckd, (float)skd };

    auto put = [&](int j, int k, float x){
        __nv_bfloat16 h = __float2bfloat16(x);
        float l = x - __bfloat162float(h);
        // N-permutation: gmem col -> storage row js
        int u  = j >> 4, rem = j & 15;
        int tt = rem >> 2, w4 = rem & 3;
        int js = (2*u + (w4 >> 1)) * 8 + 2*tt + (w4 & 1);
        // K location: chunk c, thread tq, quad q
        int c = k >> 4, tq = (k >> 2) & 3, q = k & 3;
        __nv_bfloat16* base = reinterpret_cast<__nv_bfloat16*>(&g_Wf[js*17 + c*4 + tq]);
        base[q]     = h;                       // words x,y = b0h,b1h
        base[4 + q] = __float2bfloat16(l);     // words z,w = b0l,b1l
    };
    auto write_col = [&](int n, fc v){
        fc w = cmul(kerr, v);
        put(2*m,     n,      w.re);
        put(2*m + 1, n,      w.im);
        put(2*m,     32 + n, -w.im);
        put(2*m + 1, 32 + n, w.re);
    };

    fc cur = c0, prev = {0.0f, 0.0f};
    write_col(0, cur);

    for (int n = 0; n < 31; n++) {
        float ur = __shfl_up_sync(0xffffffffu, cur.re, 1);
        float ui = __shfl_up_sync(0xffffffffu, cur.im, 1);
        if (m == 0) { ur = 0.0f; ui = 0.0f; }
        fc gc = cmul(gbar, cur);
        fc term = { sq_m * ur - gc.re, sq_m * ui - gc.im };
        fc pt = cmul(P, term);
        fc qp = cscale(cmul(Q, prev), SQ(n));
        fc next = cscale({pt.re + qp.re, pt.im + qp.im}, RSQ(n + 1));
        prev = cur; cur = next;
        write_col(n + 1, cur);
    }
}

// ============================ apply (tensor) ===============================

__device__ __forceinline__ void split2(float x, float y, uint32_t& h, uint32_t& l)
{
    uint32_t hh;
    asm("cvt.rn.bf16x2.f32 %0, %1, %2;" : "=r"(hh) : "f"(y), "f"(x)); // lo=x, hi=y
    float hx = __uint_as_float(hh << 16);
    float hy = __uint_as_float(hh & 0xffff0000u);
    float lx = x - hx;
    float ly = y - hy;
    uint32_t ll;
    asm("cvt.rn.bf16x2.f32 %0, %1, %2;" : "=r"(ll) : "f"(ly), "f"(lx));
    h = hh; l = ll;
}

__device__ __forceinline__ void mma_bf16(float* c,
                                         uint32_t a0, uint32_t a1, uint32_t a2, uint32_t a3,
                                         uint32_t b0, uint32_t b1)
{
    asm("mma.sync.aligned.m16n8k16.row.col.f32.bf16.bf16.f32 "
        "{%0,%1,%2,%3}, {%4,%5,%6,%7}, {%8,%9}, {%0,%1,%2,%3};"
        : "+f"(c[0]), "+f"(c[1]), "+f"(c[2]), "+f"(c[3])
        : "r"(a0), "r"(a1), "r"(a2), "r"(a3), "r"(b0), "r"(b1));
}

__global__ void __launch_bounds__(TPB, 2)
apply_k(const float* __restrict__ sre, const float* __restrict__ sim,
        float* __restrict__ out, int B)
{
    __shared__ uint4 sW[64 * 17];
    for (int i = threadIdx.x; i < 64 * 17; i += TPB) sW[i] = g_Wf[i];
    __syncthreads();

    const int warp = threadIdx.x >> 5;
    const int lane = threadIdx.x & 31;
    const int g    = lane >> 2;     // 0..7
    const int t    = lane & 3;      // 0..3

    const int wbase = blockIdx.x * 256 + warp * 32;   // 32 states per warp

    int row0[2], row1[2];
#pragma unroll
    for (int tile = 0; tile < 2; tile++) {
        row0[tile] = wbase + tile * 16 + g;
        row1[tile] = row0[tile] + 8;
    }

    // ---- front-batched A loads: 16x LDG.128 ----
    float4 L[16];
#pragma unroll
    for (int tile = 0; tile < 2; tile++) {
        int rc0 = (row0[tile] < B) ? row0[tile] : (B - 1);
        int rc1 = (row1[tile] < B) ? row1[tile] : (B - 1);
        const float4* pr0 = reinterpret_cast<const float4*>(sre + (size_t)rc0 * 32);
        const float4* pi0 = reinterpret_cast<const float4*>(sim + (size_t)rc0 * 32);
        const float4* pr1 = reinterpret_cast<const float4*>(sre + (size_t)rc1 * 32);
        const float4* pi1 = reinterpret_cast<const float4*>(sim + (size_t)rc1 * 32);
        L[tile * 8 + 0] = pr0[t];
        L[tile * 8 + 1] = pr0[t + 4];
        L[tile * 8 + 2] = pi0[t];
        L[tile * 8 + 3] = pi0[t + 4];
        L[tile * 8 + 4] = pr1[t];
        L[tile * 8 + 5] = pr1[t + 4];
        L[tile * 8 + 6] = pi1[t];
        L[tile * 8 + 7] = pi1[t + 4];
    }

    // A fragments: [tile][kt][reg]
    uint32_t Ah[2][4][4], Al[2][4][4];
#pragma unroll
    for (int tile = 0; tile < 2; tile++) {
#pragma unroll
        for (int kt = 0; kt < 4; kt++) {
            float4 v0 = L[tile * 8 + kt];
            float4 v1 = L[tile * 8 + 4 + kt];
            split2(v0.x, v0.y, Ah[tile][kt][0], Al[tile][kt][0]);
            split2(v0.z, v0.w, Ah[tile][kt][2], Al[tile][kt][2]);
            split2(v1.x, v1.y, Ah[tile][kt][1], Al[tile][kt][1]);
            split2(v1.z, v1.w, Ah[tile][kt][3], Al[tile][kt][3]);
        }
    }

#pragma unroll
    for (int u = 0; u < 4; u++) {
        float acc[2][2][4];                 // [ntHalf][tile][frag]
#pragma unroll
        for (int a = 0; a < 2; a++)
#pragma unroll
            for (int b = 0; b < 2; b++)
#pragma unroll
                for (int c = 0; c < 4; c++) acc[a][b][c] = 0.f;

#pragma unroll
        for (int h2 = 0; h2 < 2; h2++) {
            const int nt = 2 * u + h2;
            const uint4* bp = &sW[(nt * 8 + g) * 17 + t];
#pragma unroll
            for (int kt = 0; kt < 4; kt++) {
                uint4 b = bp[kt * 4];       // {b0h, b1h, b0l, b1l}
#pragma unroll
                for (int tile = 0; tile < 2; tile++) {
                    mma_bf16(acc[h2][tile], Ah[tile][kt][0], Ah[tile][kt][1],
                                            Ah[tile][kt][2], Ah[tile][kt][3], b.x, b.y);
                    mma_bf16(acc[h2][tile], Al[tile][kt][0], Al[tile][kt][1],
                                            Al[tile][kt][2], Al[tile][kt][3], b.x, b.y);
                    mma_bf16(acc[h2][tile], Ah[tile][kt][0], Ah[tile][kt][1],
                                            Ah[tile][kt][2], Ah[tile][kt][3], b.z, b.w);
                }
            }
        }

        // stores: gmem cols 16u + 4t .. +3 (STG.128)
        const int colb = 16 * u + 4 * t;
#pragma unroll
        for (int tile = 0; tile < 2; tile++) {
            if (row0[tile] < B) {
                float4 v = make_float4(acc[0][tile][0], acc[0][tile][1],
                                       acc[1][tile][0], acc[1][tile][1]);
                *reinterpret_cast<float4*>(out + (size_t)row0[tile] * 64 + colb) = v;
            }
            if (row1[tile] < B) {
                float4 v = make_float4(acc[0][tile][2], acc[0][tile][3],
                                       acc[1][tile][2], acc[1][tile][3]);
                *reinterpret_cast<float4*>(out + (size_t)row1[tile] * 64 + colb) = v;
            }
        }
    }
}

extern "C" void kernel_launch(void* const* d_in, const int* in_sizes, int n_in,
                              void* d_out, int out_size)
{
    const float* state_re = (const float*)d_in[0];
    const float* state_im = (const float*)d_in[1];
    const float* gamma_re = (const float*)d_in[2];
    const float* gamma_im = (const float*)d_in[3];
    const float* phi      = (const float*)d_in[4];
    const float* zeta_re  = (const float*)d_in[5];
    const float* zeta_im  = (const float*)d_in[6];
    const float* kappa    = (const float*)d_in[7];

    const int B = in_sizes[0] / 32;

    build_G<<<1, 32>>>(gamma_re, gamma_im, phi, zeta_re, zeta_im, kappa);

    const int blocks = (B + 255) / 256;   // 256 states per CTA (8 warps x 32)
    apply_k<<<blocks, TPB>>>(state_re, state_im, (float*)d_out, B);
}

// round 8
// speedup vs baseline: 1.8117x; 1.0186x over previous
#include <cuda_runtime.h>
#include <cuda_bf16.h>
#include <cstdint>

// ---------------------------------------------------------------------------
// QuantumLayer: out[b,m] = e^{i*kappa*m^2} * sum_n G[m,n] * state[b,n]
// GEMM form: out[B,64] = X[B,64] @ W[64,64], X=[re|im],
//   cols 2m/2m+1 = Re/Im (Kerr folded into W).
// bf16 mma.m16n8k16, hi/lo split: D = Xh*Wh + Xl*Wh + Xh*Wl.
//
// Round 8: ldmatrix-native W layout (1x LDSM.x4 per (nt,kt) gives all four
// B fragments), state LDGs issued before the W smem fill, 128-thread CTAs
// with 5 CTAs/SM for latency hiding.
// ---------------------------------------------------------------------------

#define TPB 128

// W in ldmatrix-native layout: 32 blocks (nt*4+kt) x 512B.
// Block: matrix0=b0h rows(g)x16B, matrix1=b1h, matrix2=b0l, matrix3=b1l.
__device__ __nv_bfloat16 g_Wb[8192];   // 16 KB

// ======================== build W (1 warp, fp32) ===========================
struct fc { float re, im; };
__device__ __forceinline__ fc cmul(fc a, fc b){ return {a.re*b.re - a.im*b.im, a.re*b.im + a.im*b.re}; }
__device__ __forceinline__ fc cadd(fc a, fc b){ return {a.re + b.re, a.im + b.im}; }
__device__ __forceinline__ fc cscale(fc a, float s){ return {a.re*s, a.im*s}; }

__global__ void build_G(const float* __restrict__ gre, const float* __restrict__ gim,
                        const float* __restrict__ phip, const float* __restrict__ zrep,
                        const float* __restrict__ zimp, const float* __restrict__ kapp)
{
    const int m = threadIdx.x;  // lane 0..31 == Fock row index
    const float gr  = gre[0],  gi  = gim[0];
    const float ph  = phip[0];
    const float zr  = zrep[0], zi  = zimp[0];
    const float kap = kapp[0];

    const float sq_m  = sqrtf((float)m);
    const float rsq_m = (m > 0) ? 1.0f / sq_m : 0.0f;
    auto SQ  = [&](int k){ return __shfl_sync(0xffffffffu, sq_m,  k); };
    auto RSQ = [&](int k){ return __shfl_sync(0xffffffffu, rsq_m, k); };

    const float r = sqrtf(zr*zr + zi*zi);
    fc eid;                                   // e^{i delta} = zeta/|zeta|
    if (r > 0.0f) { eid = { zr / r, zi / r }; } else { eid = { 1.0f, 0.0f }; }

    const float er   = expf(r);
    const float eiv  = 1.0f / er;
    const float chv  = 0.5f * (er + eiv);
    const float T    = (0.5f * (er - eiv)) / chv;  // tanh r
    const float sech = 1.0f / chv;

    float sph, cph; sincosf(ph, &sph, &cph);
    const fc eiphi  = { cph, sph };
    const fc e2iphi = cmul(eiphi, eiphi);
    const fc eidp   = cmul(eid, e2iphi);      // e^{i(delta + 2 phi)}

    const fc gamma = { gr,  gi };
    const fc gbar  = { gr, -gi };

    // g00
    const fc gb2 = cmul(gbar, gbar);
    const fc t1  = cscale(cmul(gb2, eidp), T);
    const float zr_ = -0.5f*(gr*gr + gi*gi + t1.re);
    const float zi_ = -0.5f*t1.im;
    float s0, c0p; sincosf(zi_, &s0, &c0p);
    const float ez = expf(zr_) * sqrtf(sech);
    const fc g00 = { ez * c0p, ez * s0 };

    const fc A  = cadd(gamma, cscale(cmul(gbar, eidp), T));
    const fc Bc = cscale(eidp, T);
    const fc P  = cscale(eiphi, sech);
    const fc Q  = { eid.re * T, -eid.im * T };   // e^{-i delta} tanh r

    // column 0 (serial, replicated; lane keeps its row m)
    fc c0 = g00;
    {
        fc gm1 = g00, gm2 = {0.0f, 0.0f};
        for (int k = 1; k < 32; k++) {
            fc ag = cmul(A, gm1);
            fc bg = cscale(cmul(Bc, gm2), SQ(k - 1));
            fc g  = cscale({ag.re - bg.re, ag.im - bg.im}, RSQ(k));
            if (m == k) c0 = g;
            gm2 = gm1; gm1 = g;
        }
    }

    // Kerr: angle exactly as the fp32 reference ((kap*m)*m), fp64 sincos.
    const float angf = (kap * (float)m) * (float)m;
    double skd, ckd; sincos((double)angf, &skd, &ckd);
    const fc kerr = { (float)ckd, (float)skd };

    // Write logical fragment value for (gmem col j, k) into ldmatrix layout.
    auto put = [&](int j, int k, float x){
        __nv_bfloat16 h = __float2bfloat16(x);
        float l = x - __bfloat162float(h);
        // N-permutation: gmem col -> (nt, p) storage row within nt
        int u  = j >> 4, rem = j & 15;
        int tt = rem >> 2, w4 = rem & 3;
        int nt = 2*u + (w4 >> 1);
        int p  = 2*tt + (w4 & 1);
        // K location: chunk c, thread-slot tq, quad elem q
        int c = k >> 4, tq = (k >> 2) & 3, q = k & 3;
        // ldmatrix block (nt*4+c): matrix (q>>1) hi / (2+(q>>1)) lo,
        // row p, word tq, sub-elem (q&1)
        int off = (nt*4 + c)*256 + (q >> 1)*64 + p*8 + tq*2 + (q & 1);
        g_Wb[off]       = h;
        g_Wb[off + 128] = __float2bfloat16(l);
    };
    auto write_col = [&](int n, fc v){
        fc w = cmul(kerr, v);
        put(2*m,     n,      w.re);
        put(2*m + 1, n,      w.im);
        put(2*m,     32 + n, -w.im);
        put(2*m + 1, 32 + n, w.re);
    };

    fc cur = c0, prev = {0.0f, 0.0f};
    write_col(0, cur);

    for (int n = 0; n < 31; n++) {
        float ur = __shfl_up_sync(0xffffffffu, cur.re, 1);
        float ui = __shfl_up_sync(0xffffffffu, cur.im, 1);
        if (m == 0) { ur = 0.0f; ui = 0.0f; }
        fc gc = cmul(gbar, cur);
        fc term = { sq_m * ur - gc.re, sq_m * ui - gc.im };
        fc pt = cmul(P, term);
        fc qp = cscale(cmul(Q, prev), SQ(n));
        fc next = cscale({pt.re + qp.re, pt.im + qp.im}, RSQ(n + 1));
        prev = cur; cur = next;
        write_col(n + 1, cur);
    }
}

// ============================ apply (tensor) ===============================

__device__ __forceinline__ void split2(float x, float y, uint32_t& h, uint32_t& l)
{
    uint32_t hh;
    asm("cvt.rn.bf16x2.f32 %0, %1, %2;" : "=r"(hh) : "f"(y), "f"(x)); // lo=x, hi=y
    float hx = __uint_as_float(hh << 16);
    float hy = __uint_as_float(hh & 0xffff0000u);
    float lx = x - hx;
    float ly = y - hy;
    uint32_t ll;
    asm("cvt.rn.bf16x2.f32 %0, %1, %2;" : "=r"(ll) : "f"(ly), "f"(lx));
    h = hh; l = ll;
}

__device__ __forceinline__ void mma_bf16(float* c,
                                         uint32_t a0, uint32_t a1, uint32_t a2, uint32_t a3,
                                         uint32_t b0, uint32_t b1)
{
    asm("mma.sync.aligned.m16n8k16.row.col.f32.bf16.bf16.f32 "
        "{%0,%1,%2,%3}, {%4,%5,%6,%7}, {%8,%9}, {%0,%1,%2,%3};"
        : "+f"(c[0]), "+f"(c[1]), "+f"(c[2]), "+f"(c[3])
        : "r"(a0), "r"(a1), "r"(a2), "r"(a3), "r"(b0), "r"(b1));
}

template <bool FULL>
__device__ __forceinline__ void apply_body(
    const float* __restrict__ sre, const float* __restrict__ sim,
    float* __restrict__ out, int B, __nv_bfloat16* sW)
{
    const int warp = threadIdx.x >> 5;
    const int lane = threadIdx.x & 31;
    const int g    = lane >> 2;     // 0..7
    const int t    = lane & 3;      // 0..3

    const int wbase = blockIdx.x * (TPB / 32 * 32) + warp * 32;   // 32 states/warp

    int row0[2], row1[2];
#pragma unroll
    for (int tile = 0; tile < 2; tile++) {
        row0[tile] = wbase + tile * 16 + g;
        row1[tile] = row0[tile] + 8;
    }

    // ---- front-batched state loads FIRST: 16x LDG.128 ----
    float4 L[16];
#pragma unroll
    for (int tile = 0; tile < 2; tile++) {
        int rc0 = row0[tile], rc1 = row1[tile];
        if (!FULL) { rc0 = (rc0 < B) ? rc0 : (B - 1); rc1 = (rc1 < B) ? rc1 : (B - 1); }
        const float4* pr0 = reinterpret_cast<const float4*>(sre + (size_t)rc0 * 32);
        const float4* pi0 = reinterpret_cast<const float4*>(sim + (size_t)rc0 * 32);
        const float4* pr1 = reinterpret_cast<const float4*>(sre + (size_t)rc1 * 32);
        const float4* pi1 = reinterpret_cast<const float4*>(sim + (size_t)rc1 * 32);
        L[tile * 8 + 0] = pr0[t];
        L[tile * 8 + 1] = pr0[t + 4];
        L[tile * 8 + 2] = pi0[t];
        L[tile * 8 + 3] = pi0[t + 4];
        L[tile * 8 + 4] = pr1[t];
        L[tile * 8 + 5] = pr1[t + 4];
        L[tile * 8 + 6] = pi1[t];
        L[tile * 8 + 7] = pi1[t + 4];
    }

    // ---- W into shared (overlaps the state-load latency) ----
    {
        const uint4* src = reinterpret_cast<const uint4*>(g_Wb);
        uint4* dst = reinterpret_cast<uint4*>(sW);
        for (int i = threadIdx.x; i < 1024; i += TPB) dst[i] = src[i];
    }
    __syncthreads();

    // ---- convert A fragments (tile 0 then tile 1; L dies progressively) ----
    uint32_t Ah[2][4][4], Al[2][4][4];
#pragma unroll
    for (int tile = 0; tile < 2; tile++) {
#pragma unroll
        for (int kt = 0; kt < 4; kt++) {
            float4 v0 = L[tile * 8 + kt];
            float4 v1 = L[tile * 8 + 4 + kt];
            split2(v0.x, v0.y, Ah[tile][kt][0], Al[tile][kt][0]);
            split2(v0.z, v0.w, Ah[tile][kt][2], Al[tile][kt][2]);
            split2(v1.x, v1.y, Ah[tile][kt][1], Al[tile][kt][1]);
            split2(v1.z, v1.w, Ah[tile][kt][3], Al[tile][kt][3]);
        }
    }

    const uint32_t swb = (uint32_t)__cvta_generic_to_shared(sW) + lane * 16;

#pragma unroll
    for (int u = 0; u < 4; u++) {
        float acc[2][2][4];                 // [ntHalf][tile][frag]
#pragma unroll
        for (int a = 0; a < 2; a++)
#pragma unroll
            for (int b = 0; b < 2; b++)
#pragma unroll
                for (int c = 0; c < 4; c++) acc[a][b][c] = 0.f;

#pragma unroll
        for (int h2 = 0; h2 < 2; h2++) {
            const int nt = 2 * u + h2;
#pragma unroll
            for (int kt = 0; kt < 4; kt++) {
                uint32_t b0h, b1h, b0l, b1l;
                asm volatile(
                    "ldmatrix.sync.aligned.m8n8.x4.shared.b16 {%0,%1,%2,%3}, [%4];"
                    : "=r"(b0h), "=r"(b1h), "=r"(b0l), "=r"(b1l)
                    : "r"(swb + (uint32_t)((nt * 4 + kt) * 512)));
#pragma unroll
                for (int tile = 0; tile < 2; tile++) {
                    mma_bf16(acc[h2][tile], Ah[tile][kt][0], Ah[tile][kt][1],
                                            Ah[tile][kt][2], Ah[tile][kt][3], b0h, b1h);
                    mma_bf16(acc[h2][tile], Al[tile][kt][0], Al[tile][kt][1],
                                            Al[tile][kt][2], Al[tile][kt][3], b0h, b1h);
                    mma_bf16(acc[h2][tile], Ah[tile][kt][0], Ah[tile][kt][1],
                                            Ah[tile][kt][2], Ah[tile][kt][3], b0l, b1l);
                }
            }
        }

        // stores: gmem cols 16u + 4t .. +3 (STG.128)
        const int colb = 16 * u + 4 * t;
#pragma unroll
        for (int tile = 0; tile < 2; tile++) {
            if (FULL || row0[tile] < B) {
                float4 v = make_float4(acc[0][tile][0], acc[0][tile][1],
                                       acc[1][tile][0], acc[1][tile][1]);
                *reinterpret_cast<float4*>(out + (size_t)row0[tile] * 64 + colb) = v;
            }
            if (FULL || row1[tile] < B) {
                float4 v = make_float4(acc[0][tile][2], acc[0][tile][3],
                                       acc[1][tile][2], acc[1][tile][3]);
                *reinterpret_cast<float4*>(out + (size_t)row1[tile] * 64 + colb) = v;
            }
        }
    }
}

template <bool FULL>
__global__ void __launch_bounds__(TPB, 5)
apply_k(const float* __restrict__ sre, const float* __restrict__ sim,
        float* __restrict__ out, int B)
{
    __shared__ __nv_bfloat16 sW[8192];   // 16 KB, ldmatrix-native
    apply_body<FULL>(sre, sim, out, B, sW);
}

extern "C" void kernel_launch(void* const* d_in, const int* in_sizes, int n_in,
                              void* d_out, int out_size)
{
    const float* state_re = (const float*)d_in[0];
    const float* state_im = (const float*)d_in[1];
    const float* gamma_re = (const float*)d_in[2];
    const float* gamma_im = (const float*)d_in[3];
    const float* phi      = (const float*)d_in[4];
    const float* zeta_re  = (const float*)d_in[5];
    const float* zeta_im  = (const float*)d_in[6];
    const float* kappa    = (const float*)d_in[7];

    const int B = in_sizes[0] / 32;

    build_G<<<1, 32>>>(gamma_re, gamma_im, phi, zeta_re, zeta_im, kappa);

    const int blocks = (B + TPB - 1) / TPB;   // 128 states per CTA (4 warps x 32)
    if ((B & (TPB - 1)) == 0)
        apply_k<true><<<blocks, TPB>>>(state_re, state_im, (float*)d_out, B);
    else
        apply_k<false><<<blocks, TPB>>>(state_re, state_im, (float*)d_out, B);
}

// round 9
// speedup vs baseline: 2.1403x; 1.1813x over previous
#include <cuda_runtime.h>
#include <cuda_fp16.h>
#include <cstdint>

// ---------------------------------------------------------------------------
// QuantumLayer: out[b,m] = e^{i*kappa*m^2} * sum_n G[m,n] * state[b,n]
// GEMM form: out[B,64] = X[B,64] @ W[64,64], X=[re|im],
//   cols 2m/2m+1 = Re/Im (Kerr folded into W).
//
// Round 9: fp16 2-product scheme  D = X_f16*Wh + X_f16*Wl
//   (X single fp16: err ~2^-11/sqrt3 ~ 2.8e-4 << 1e-3; W hi/lo fp16).
// Halves A-fragment registers (64->32) and mma count (3->2 products),
// enabling 7 CTAs/SM for latency hiding. W fill via cp.async.
// ---------------------------------------------------------------------------

#define TPB 128

// W in ldmatrix-native layout: 32 blocks (nt*4+kt) x 512B.
// Block: matrix0=b0h, matrix1=b1h, matrix2=b0l, matrix3=b1l (8x8 fp16 each).
__device__ __half g_Wb[8192];   // 16 KB

// ======================== build W (1 warp, fp32) ===========================
struct fc { float re, im; };
__device__ __forceinline__ fc cmul(fc a, fc b){ return {a.re*b.re - a.im*b.im, a.re*b.im + a.im*b.re}; }
__device__ __forceinline__ fc cadd(fc a, fc b){ return {a.re + b.re, a.im + b.im}; }
__device__ __forceinline__ fc cscale(fc a, float s){ return {a.re*s, a.im*s}; }

__global__ void build_G(const float* __restrict__ gre, const float* __restrict__ gim,
                        const float* __restrict__ phip, const float* __restrict__ zrep,
                        const float* __restrict__ zimp, const float* __restrict__ kapp)
{
    const int m = threadIdx.x;  // lane 0..31 == Fock row index
    const float gr  = gre[0],  gi  = gim[0];
    const float ph  = phip[0];
    const float zr  = zrep[0], zi  = zimp[0];
    const float kap = kapp[0];

    const float sq_m  = sqrtf((float)m);
    const float rsq_m = (m > 0) ? 1.0f / sq_m : 0.0f;
    auto SQ  = [&](int k){ return __shfl_sync(0xffffffffu, sq_m,  k); };
    auto RSQ = [&](int k){ return __shfl_sync(0xffffffffu, rsq_m, k); };

    const float r = sqrtf(zr*zr + zi*zi);
    fc eid;                                   // e^{i delta} = zeta/|zeta|
    if (r > 0.0f) { eid = { zr / r, zi / r }; } else { eid = { 1.0f, 0.0f }; }

    const float er   = expf(r);
    const float eiv  = 1.0f / er;
    const float chv  = 0.5f * (er + eiv);
    const float T    = (0.5f * (er - eiv)) / chv;  // tanh r
    const float sech = 1.0f / chv;

    float sph, cph; sincosf(ph, &sph, &cph);
    const fc eiphi  = { cph, sph };
    const fc e2iphi = cmul(eiphi, eiphi);
    const fc eidp   = cmul(eid, e2iphi);      // e^{i(delta + 2 phi)}

    const fc gamma = { gr,  gi };
    const fc gbar  = { gr, -gi };

    // g00
    const fc gb2 = cmul(gbar, gbar);
    const fc t1  = cscale(cmul(gb2, eidp), T);
    const float zr_ = -0.5f*(gr*gr + gi*gi + t1.re);
    const float zi_ = -0.5f*t1.im;
    float s0, c0p; sincosf(zi_, &s0, &c0p);
    const float ez = expf(zr_) * sqrtf(sech);
    const fc g00 = { ez * c0p, ez * s0 };

    const fc A  = cadd(gamma, cscale(cmul(gbar, eidp), T));
    const fc Bc = cscale(eidp, T);
    const fc P  = cscale(eiphi, sech);
    const fc Q  = { eid.re * T, -eid.im * T };   // e^{-i delta} tanh r

    // column 0 (serial, replicated; lane keeps its row m)
    fc c0 = g00;
    {
        fc gm1 = g00, gm2 = {0.0f, 0.0f};
        for (int k = 1; k < 32; k++) {
            fc ag = cmul(A, gm1);
            fc bg = cscale(cmul(Bc, gm2), SQ(k - 1));
            fc g  = cscale({ag.re - bg.re, ag.im - bg.im}, RSQ(k));
            if (m == k) c0 = g;
            gm2 = gm1; gm1 = g;
        }
    }

    // Kerr: angle exactly as the fp32 reference ((kap*m)*m), fp64 sincos.
    const float angf = (kap * (float)m) * (float)m;
    double skd, ckd; sincos((double)angf, &skd, &ckd);
    const fc kerr = { (float)ckd, (float)skd };

    // Write logical fragment value for (gmem col j, k) into ldmatrix layout.
    auto put = [&](int j, int k, float x){
        __half h = __float2half_rn(x);
        float l = x - __half2float(h);
        // N-permutation: gmem col -> (nt, p) storage row within nt
        int u  = j >> 4, rem = j & 15;
        int tt = rem >> 2, w4 = rem & 3;
        int nt = 2*u + (w4 >> 1);
        int p  = 2*tt + (w4 & 1);
        // K location: chunk c, thread-slot tq, quad elem q
        int c = k >> 4, tq = (k >> 2) & 3, q = k & 3;
        // ldmatrix block (nt*4+c): matrix (q>>1) hi / (2+(q>>1)) lo,
        // row p, word tq, sub-elem (q&1)
        int off = (nt*4 + c)*256 + (q >> 1)*64 + p*8 + tq*2 + (q & 1);
        g_Wb[off]       = h;
        g_Wb[off + 128] = __float2half_rn(l);
    };
    auto write_col = [&](int n, fc v){
        fc w = cmul(kerr, v);
        put(2*m,     n,      w.re);
        put(2*m + 1, n,      w.im);
        put(2*m,     32 + n, -w.im);
        put(2*m + 1, 32 + n, w.re);
    };

    fc cur = c0, prev = {0.0f, 0.0f};
    write_col(0, cur);

    for (int n = 0; n < 31; n++) {
        float ur = __shfl_up_sync(0xffffffffu, cur.re, 1);
        float ui = __shfl_up_sync(0xffffffffu, cur.im, 1);
        if (m == 0) { ur = 0.0f; ui = 0.0f; }
        fc gc = cmul(gbar, cur);
        fc term = { sq_m * ur - gc.re, sq_m * ui - gc.im };
        fc pt = cmul(P, term);
        fc qp = cscale(cmul(Q, prev), SQ(n));
        fc next = cscale({pt.re + qp.re, pt.im + qp.im}, RSQ(n + 1));
        prev = cur; cur = next;
        write_col(n + 1, cur);
    }
}

// ============================ apply (tensor) ===============================

__device__ __forceinline__ uint32_t pack_h2(float x, float y)
{
    uint32_t r;  // lo = x, hi = y
    asm("cvt.rn.f16x2.f32 %0, %1, %2;" : "=r"(r) : "f"(y), "f"(x));
    return r;
}

__device__ __forceinline__ void mma_f16(float* c,
                                        uint32_t a0, uint32_t a1, uint32_t a2, uint32_t a3,
                                        uint32_t b0, uint32_t b1)
{
    asm("mma.sync.aligned.m16n8k16.row.col.f32.f16.f16.f32 "
        "{%0,%1,%2,%3}, {%4,%5,%6,%7}, {%8,%9}, {%0,%1,%2,%3};"
        : "+f"(c[0]), "+f"(c[1]), "+f"(c[2]), "+f"(c[3])
        : "r"(a0), "r"(a1), "r"(a2), "r"(a3), "r"(b0), "r"(b1));
}

template <bool FULL>
__device__ __forceinline__ void apply_body(
    const float* __restrict__ sre, const float* __restrict__ sim,
    float* __restrict__ out, int B, __half* sW)
{
    const int warp = threadIdx.x >> 5;
    const int lane = threadIdx.x & 31;
    const int g    = lane >> 2;     // 0..7
    const int t    = lane & 3;      // 0..3

    const int wbase = blockIdx.x * TPB + warp * 32;   // 32 states/warp

    int row0[2], row1[2];
#pragma unroll
    for (int tile = 0; tile < 2; tile++) {
        row0[tile] = wbase + tile * 16 + g;
        row1[tile] = row0[tile] + 8;
    }

    // ---- front-batched state loads FIRST: 16x LDG.128 ----
    float4 L[16];
#pragma unroll
    for (int tile = 0; tile < 2; tile++) {
        int rc0 = row0[tile], rc1 = row1[tile];
        if (!FULL) { rc0 = (rc0 < B) ? rc0 : (B - 1); rc1 = (rc1 < B) ? rc1 : (B - 1); }
        const float4* pr0 = reinterpret_cast<const float4*>(sre + (size_t)rc0 * 32);
        const float4* pi0 = reinterpret_cast<const float4*>(sim + (size_t)rc0 * 32);
        const float4* pr1 = reinterpret_cast<const float4*>(sre + (size_t)rc1 * 32);
        const float4* pi1 = reinterpret_cast<const float4*>(sim + (size_t)rc1 * 32);
        L[tile * 8 + 0] = pr0[t];
        L[tile * 8 + 1] = pr0[t + 4];
        L[tile * 8 + 2] = pi0[t];
        L[tile * 8 + 3] = pi0[t + 4];
        L[tile * 8 + 4] = pr1[t];
        L[tile * 8 + 5] = pr1[t + 4];
        L[tile * 8 + 6] = pi1[t];
        L[tile * 8 + 7] = pi1[t + 4];
    }

    // ---- W into shared via cp.async (no reg round-trip) ----
    {
        uint32_t sbase = (uint32_t)__cvta_generic_to_shared(sW);
        const char* gbase = reinterpret_cast<const char*>(g_Wb);
#pragma unroll
        for (int i = 0; i < 8; i++) {
            int idx = threadIdx.x + i * TPB;       // 1024 chunks of 16B
            asm volatile("cp.async.ca.shared.global [%0], [%1], 16;"
                         :: "r"(sbase + idx * 16), "l"(gbase + idx * 16));
        }
        asm volatile("cp.async.commit_group;");
        asm volatile("cp.async.wait_group 0;");
    }
    __syncthreads();

    // ---- convert A fragments (single fp16, lo part dropped) ----
    uint32_t Af[2][4][4];
#pragma unroll
    for (int tile = 0; tile < 2; tile++) {
#pragma unroll
        for (int kt = 0; kt < 4; kt++) {
            float4 v0 = L[tile * 8 + kt];
            float4 v1 = L[tile * 8 + 4 + kt];
            Af[tile][kt][0] = pack_h2(v0.x, v0.y);
            Af[tile][kt][2] = pack_h2(v0.z, v0.w);
            Af[tile][kt][1] = pack_h2(v1.x, v1.y);
            Af[tile][kt][3] = pack_h2(v1.z, v1.w);
        }
    }

    const uint32_t swb = (uint32_t)__cvta_generic_to_shared(sW) + lane * 16;

#pragma unroll
    for (int u = 0; u < 4; u++) {
        float acc[2][2][4];                 // [ntHalf][tile][frag]
#pragma unroll
        for (int a = 0; a < 2; a++)
#pragma unroll
            for (int b = 0; b < 2; b++)
#pragma unroll
                for (int c = 0; c < 4; c++) acc[a][b][c] = 0.f;

#pragma unroll
        for (int h2 = 0; h2 < 2; h2++) {
            const int nt = 2 * u + h2;
#pragma unroll
            for (int kt = 0; kt < 4; kt++) {
                uint32_t b0h, b1h, b0l, b1l;
                asm volatile(
                    "ldmatrix.sync.aligned.m8n8.x4.shared.b16 {%0,%1,%2,%3}, [%4];"
                    : "=r"(b0h), "=r"(b1h), "=r"(b0l), "=r"(b1l)
                    : "r"(swb + (uint32_t)((nt * 4 + kt) * 512)));
#pragma unroll
                for (int tile = 0; tile < 2; tile++) {
                    mma_f16(acc[h2][tile], Af[tile][kt][0], Af[tile][kt][1],
                                           Af[tile][kt][2], Af[tile][kt][3], b0h, b1h);
                    mma_f16(acc[h2][tile], Af[tile][kt][0], Af[tile][kt][1],
                                           Af[tile][kt][2], Af[tile][kt][3], b0l, b1l);
                }
            }
        }

        // stores: gmem cols 16u + 4t .. +3 (STG.128)
        const int colb = 16 * u + 4 * t;
#pragma unroll
        for (int tile = 0; tile < 2; tile++) {
            if (FULL || row0[tile] < B) {
                float4 v = make_float4(acc[0][tile][0], acc[0][tile][1],
                                       acc[1][tile][0], acc[1][tile][1]);
                *reinterpret_cast<float4*>(out + (size_t)row0[tile] * 64 + colb) = v;
            }
            if (FULL || row1[tile] < B) {
                float4 v = make_float4(acc[0][tile][2], acc[0][tile][3],
                                       acc[1][tile][2], acc[1][tile][3]);
                *reinterpret_cast<float4*>(out + (size_t)row1[tile] * 64 + colb) = v;
            }
        }
    }
}

template <bool FULL>
__global__ void __launch_bounds__(TPB, 7)
apply_k(const float* __restrict__ sre, const float* __restrict__ sim,
        float* __restrict__ out, int B)
{
    __shared__ __half sW[8192];   // 16 KB, ldmatrix-native
    apply_body<FULL>(sre, sim, out, B, sW);
}

extern "C" void kernel_launch(void* const* d_in, const int* in_sizes, int n_in,
                              void* d_out, int out_size)
{
    const float* state_re = (const float*)d_in[0];
    const float* state_im = (const float*)d_in[1];
    const float* gamma_re = (const float*)d_in[2];
    const float* gamma_im = (const float*)d_in[3];
    const float* phi      = (const float*)d_in[4];
    const float* zeta_re  = (const float*)d_in[5];
    const float* zeta_im  = (const float*)d_in[6];
    const float* kappa    = (const float*)d_in[7];

    const int B = in_sizes[0] / 32;

    build_G<<<1, 32>>>(gamma_re, gamma_im, phi, zeta_re, zeta_im, kappa);

    const int blocks = (B + TPB - 1) / TPB;   // 128 states per CTA (4 warps x 32)
    if ((B & (TPB - 1)) == 0)
        apply_k<true><<<blocks, TPB>>>(state_re, state_im, (float*)d_out, B);
    else
        apply_k<false><<<blocks, TPB>>>(state_re, state_im, (float*)d_out, B);
}

// round 10
// speedup vs baseline: 2.1674x; 1.0127x over previous
#include <cuda_runtime.h>
#include <cuda_fp16.h>
#include <cstdint>

// ---------------------------------------------------------------------------
// QuantumLayer: out[b,m] = e^{i*kappa*m^2} * sum_n G[m,n] * state[b,n]
// GEMM form: out[B,64] = X[B,64] @ W[64,64], X=[re|im],
//   cols 2m/2m+1 = Re/Im (Kerr folded into W).
//
// fp16 2-product scheme  D = X_f16*Wh + X_f16*Wl  (validated R9: rel ~2.1e-4)
// Round 10: software-pipelined load/convert (peak 8 live float4) to hit
// 64 regs -> 8 CTAs/SM; build_G epilogue parallelized across 4 warps.
// ---------------------------------------------------------------------------

#define TPB 128

// W in ldmatrix-native layout: 32 blocks (nt*4+kt) x 512B.
// Block: matrix0=b0h, matrix1=b1h, matrix2=b0l, matrix3=b1l (8x8 fp16 each).
__device__ __half g_Wb[8192];   // 16 KB

// ======================== build W (4 warps, fp32) ==========================
struct fc { float re, im; };
__device__ __forceinline__ fc cmul(fc a, fc b){ return {a.re*b.re - a.im*b.im, a.re*b.im + a.im*b.re}; }
__device__ __forceinline__ fc cadd(fc a, fc b){ return {a.re + b.re, a.im + b.im}; }
__device__ __forceinline__ fc cscale(fc a, float s){ return {a.re*s, a.im*s}; }

__global__ void build_G(const float* __restrict__ gre, const float* __restrict__ gim,
                        const float* __restrict__ phip, const float* __restrict__ zrep,
                        const float* __restrict__ zimp, const float* __restrict__ kapp)
{
    const int m   = threadIdx.x & 31;   // lane == Fock row index
    const int wid = threadIdx.x >> 5;   // 4 warps replicate recurrence,
                                        // each does 1 of the 4 puts per col
    const float gr  = gre[0],  gi  = gim[0];
    const float ph  = phip[0];
    const float zr  = zrep[0], zi  = zimp[0];
    const float kap = kapp[0];

    const float sq_m  = sqrtf((float)m);
    const float rsq_m = (m > 0) ? 1.0f / sq_m : 0.0f;
    auto SQ  = [&](int k){ return __shfl_sync(0xffffffffu, sq_m,  k); };
    auto RSQ = [&](int k){ return __shfl_sync(0xffffffffu, rsq_m, k); };

    const float r = sqrtf(zr*zr + zi*zi);
    fc eid;                                   // e^{i delta} = zeta/|zeta|
    if (r > 0.0f) { eid = { zr / r, zi / r }; } else { eid = { 1.0f, 0.0f }; }

    const float er   = expf(r);
    const float eiv  = 1.0f / er;
    const float chv  = 0.5f * (er + eiv);
    const float T    = (0.5f * (er - eiv)) / chv;  // tanh r
    const float sech = 1.0f / chv;

    float sph, cph; sincosf(ph, &sph, &cph);
    const fc eiphi  = { cph, sph };
    const fc e2iphi = cmul(eiphi, eiphi);
    const fc eidp   = cmul(eid, e2iphi);      // e^{i(delta + 2 phi)}

    const fc gamma = { gr,  gi };
    const fc gbar  = { gr, -gi };

    // g00
    const fc gb2 = cmul(gbar, gbar);
    const fc t1  = cscale(cmul(gb2, eidp), T);
    const float zr_ = -0.5f*(gr*gr + gi*gi + t1.re);
    const float zi_ = -0.5f*t1.im;
    float s0, c0p; sincosf(zi_, &s0, &c0p);
    const float ez = expf(zr_) * sqrtf(sech);
    const fc g00 = { ez * c0p, ez * s0 };

    const fc A  = cadd(gamma, cscale(cmul(gbar, eidp), T));
    const fc Bc = cscale(eidp, T);
    const fc P  = cscale(eiphi, sech);
    const fc Q  = { eid.re * T, -eid.im * T };   // e^{-i delta} tanh r

    // column 0 (serial, replicated; lane keeps its row m)
    fc c0 = g00;
    {
        fc gm1 = g00, gm2 = {0.0f, 0.0f};
        for (int k = 1; k < 32; k++) {
            fc ag = cmul(A, gm1);
            fc bg = cscale(cmul(Bc, gm2), SQ(k - 1));
            fc g  = cscale({ag.re - bg.re, ag.im - bg.im}, RSQ(k));
            if (m == k) c0 = g;
            gm2 = gm1; gm1 = g;
        }
    }

    // Kerr: angle exactly as the fp32 reference ((kap*m)*m), fp64 sincos.
    const float angf = (kap * (float)m) * (float)m;
    double skd, ckd; sincos((double)angf, &skd, &ckd);
    const fc kerr = { (float)ckd, (float)skd };

    // Write logical fragment value for (gmem col j, k) into ldmatrix layout.
    auto put = [&](int j, int k, float x){
        __half h = __float2half_rn(x);
        float l = x - __half2float(h);
        // N-permutation: gmem col -> (nt, p) storage row within nt
        int u  = j >> 4, rem = j & 15;
        int tt = rem >> 2, w4 = rem & 3;
        int nt = 2*u + (w4 >> 1);
        int p  = 2*tt + (w4 & 1);
        // K location: chunk c, thread-slot tq, quad elem q
        int c = k >> 4, tq = (k >> 2) & 3, q = k & 3;
        int off = (nt*4 + c)*256 + (q >> 1)*64 + p*8 + tq*2 + (q & 1);
        g_Wb[off]       = h;
        g_Wb[off + 128] = __float2half_rn(l);
    };
    // Each warp handles exactly one of the 4 writes per (m, n).
    auto write_col = [&](int n, fc v){
        fc w = cmul(kerr, v);
        switch (wid) {
            case 0: put(2*m,     n,      w.re); break;
            case 1: put(2*m + 1, n,      w.im); break;
            case 2: put(2*m,     32 + n, -w.im); break;
            default: put(2*m + 1, 32 + n, w.re); break;
        }
    };

    fc cur = c0, prev = {0.0f, 0.0f};
    write_col(0, cur);

    for (int n = 0; n < 31; n++) {
        float ur = __shfl_up_sync(0xffffffffu, cur.re, 1);
        float ui = __shfl_up_sync(0xffffffffu, cur.im, 1);
        if (m == 0) { ur = 0.0f; ui = 0.0f; }
        fc gc = cmul(gbar, cur);
        fc term = { sq_m * ur - gc.re, sq_m * ui - gc.im };
        fc pt = cmul(P, term);
        fc qp = cscale(cmul(Q, prev), SQ(n));
        fc next = cscale({pt.re + qp.re, pt.im + qp.im}, RSQ(n + 1));
        prev = cur; cur = next;
        write_col(n + 1, cur);
    }
}

// ============================ apply (tensor) ===============================

__device__ __forceinline__ uint32_t pack_h2(float x, float y)
{
    uint32_t r;  // lo = x, hi = y
    asm("cvt.rn.f16x2.f32 %0, %1, %2;" : "=r"(r) : "f"(y), "f"(x));
    return r;
}

__device__ __forceinline__ void mma_f16(float* c,
                                        uint32_t a0, uint32_t a1, uint32_t a2, uint32_t a3,
                                        uint32_t b0, uint32_t b1)
{
    asm("mma.sync.aligned.m16n8k16.row.col.f32.f16.f16.f32 "
        "{%0,%1,%2,%3}, {%4,%5,%6,%7}, {%8,%9}, {%0,%1,%2,%3};"
        : "+f"(c[0]), "+f"(c[1]), "+f"(c[2]), "+f"(c[3])
        : "r"(a0), "r"(a1), "r"(a2), "r"(a3), "r"(b0), "r"(b1));
}

template <bool FULL>
__device__ __forceinline__ void apply_body(
    const float* __restrict__ sre, const float* __restrict__ sim,
    float* __restrict__ out, int B, __half* sW)
{
    const int warp = threadIdx.x >> 5;
    const int lane = threadIdx.x & 31;
    const int g    = lane >> 2;     // 0..7
    const int t    = lane & 3;      // 0..3

    const int wbase = blockIdx.x * TPB + warp * 32;   // 32 states/warp

    int row0[2], row1[2];
#pragma unroll
    for (int tile = 0; tile < 2; tile++) {
        row0[tile] = wbase + tile * 16 + g;
        row1[tile] = row0[tile] + 8;
    }

    // group grp (0..3): tile = grp>>1, row-sel = grp&1. 4 float4 per group.
    auto load_grp = [&](int grp, float4& a, float4& b, float4& c, float4& d){
        const int tile = grp >> 1, rs = grp & 1;
        int rc = rs ? row1[tile] : row0[tile];
        if (!FULL) rc = (rc < B) ? rc : (B - 1);
        const float4* pr = reinterpret_cast<const float4*>(sre + (size_t)rc * 32);
        const float4* pi = reinterpret_cast<const float4*>(sim + (size_t)rc * 32);
        a = pr[t]; b = pr[t + 4]; c = pi[t]; d = pi[t + 4];
    };

    uint32_t Af[2][4][4];
    auto conv_grp = [&](int grp, float4 a, float4 b, float4 c, float4 d){
        const int tile = grp >> 1, rs = grp & 1;
        Af[tile][0][0 + rs] = pack_h2(a.x, a.y);
        Af[tile][0][2 + rs] = pack_h2(a.z, a.w);
        Af[tile][1][0 + rs] = pack_h2(b.x, b.y);
        Af[tile][1][2 + rs] = pack_h2(b.z, b.w);
        Af[tile][2][0 + rs] = pack_h2(c.x, c.y);
        Af[tile][2][2 + rs] = pack_h2(c.z, c.w);
        Af[tile][3][0 + rs] = pack_h2(d.x, d.y);
        Af[tile][3][2 + rs] = pack_h2(d.z, d.w);
    };

    // ---- pipelined loads/converts: peak 8 live float4 ----
    float4 a, b, c, d;
    load_grp(0, a, b, c, d);

    // W into shared via cp.async (independent of the state loads)
    {
        uint32_t sbase = (uint32_t)__cvta_generic_to_shared(sW);
        const char* gbase = reinterpret_cast<const char*>(g_Wb);
#pragma unroll
        for (int i = 0; i < 8; i++) {
            int idx = threadIdx.x + i * TPB;       // 1024 chunks of 16B
            asm volatile("cp.async.ca.shared.global [%0], [%1], 16;"
                         :: "r"(sbase + idx * 16), "l"(gbase + idx * 16));
        }
        asm volatile("cp.async.commit_group;");
    }

#pragma unroll
    for (int grp = 0; grp < 4; grp++) {
        float4 a2, b2, c2, d2;
        if (grp < 3) load_grp(grp + 1, a2, b2, c2, d2);
        conv_grp(grp, a, b, c, d);
        a = a2; b = b2; c = c2; d = d2;
    }

    asm volatile("cp.async.wait_group 0;");
    __syncthreads();

    const uint32_t swb = (uint32_t)__cvta_generic_to_shared(sW) + lane * 16;

#pragma unroll
    for (int u = 0; u < 4; u++) {
        float acc[2][2][4];                 // [ntHalf][tile][frag]
#pragma unroll
        for (int x = 0; x < 2; x++)
#pragma unroll
            for (int y = 0; y < 2; y++)
#pragma unroll
                for (int z = 0; z < 4; z++) acc[x][y][z] = 0.f;

#pragma unroll
        for (int h2 = 0; h2 < 2; h2++) {
            const int nt = 2 * u + h2;
#pragma unroll
            for (int kt = 0; kt < 4; kt++) {
                uint32_t b0h, b1h, b0l, b1l;
                asm volatile(
                    "ldmatrix.sync.aligned.m8n8.x4.shared.b16 {%0,%1,%2,%3}, [%4];"
                    : "=r"(b0h), "=r"(b1h), "=r"(b0l), "=r"(b1l)
                    : "r"(swb + (uint32_t)((nt * 4 + kt) * 512)));
#pragma unroll
                for (int tile = 0; tile < 2; tile++) {
                    mma_f16(acc[h2][tile], Af[tile][kt][0], Af[tile][kt][1],
                                           Af[tile][kt][2], Af[tile][kt][3], b0h, b1h);
                    mma_f16(acc[h2][tile], Af[tile][kt][0], Af[tile][kt][1],
                                           Af[tile][kt][2], Af[tile][kt][3], b0l, b1l);
                }
            }
        }

        // stores: gmem cols 16u + 4t .. +3 (STG.128)
        const int colb = 16 * u + 4 * t;
#pragma unroll
        for (int tile = 0; tile < 2; tile++) {
            if (FULL || row0[tile] < B) {
                float4 v = make_float4(acc[0][tile][0], acc[0][tile][1],
                                       acc[1][tile][0], acc[1][tile][1]);
                *reinterpret_cast<float4*>(out + (size_t)row0[tile] * 64 + colb) = v;
            }
            if (FULL || row1[tile] < B) {
                float4 v = make_float4(acc[0][tile][2], acc[0][tile][3],
                                       acc[1][tile][2], acc[1][tile][3]);
                *reinterpret_cast<float4*>(out + (size_t)row1[tile] * 64 + colb) = v;
            }
        }
    }
}

template <bool FULL>
__global__ void __launch_bounds__(TPB, 8)
apply_k(const float* __restrict__ sre, const float* __restrict__ sim,
        float* __restrict__ out, int B)
{
    __shared__ __half sW[8192];   // 16 KB, ldmatrix-native
    apply_body<FULL>(sre, sim, out, B, sW);
}

extern "C" void kernel_launch(void* const* d_in, const int* in_sizes, int n_in,
                              void* d_out, int out_size)
{
    const float* state_re = (const float*)d_in[0];
    const float* state_im = (const float*)d_in[1];
    const float* gamma_re = (const float*)d_in[2];
    const float* gamma_im = (const float*)d_in[3];
    const float* phi      = (const float*)d_in[4];
    const float* zeta_re  = (const float*)d_in[5];
    const float* zeta_im  = (const float*)d_in[6];
    const float* kappa    = (const float*)d_in[7];

    const int B = in_sizes[0] / 32;

    build_G<<<1, 128>>>(gamma_re, gamma_im, phi, zeta_re, zeta_im, kappa);

    const int blocks = (B + TPB - 1) / TPB;   // 128 states per CTA (4 warps x 32)
    if ((B & (TPB - 1)) == 0)
        apply_k<true><<<blocks, TPB>>>(state_re, state_im, (float*)d_out, B);
    else
        apply_k<false><<<blocks, TPB>>>(state_re, state_im, (float*)d_out, B);
}